// round 6
// baseline (speedup 1.0000x reference)
#include <cuda_runtime.h>
#include <cuda_bf16.h>
#include <math.h>

#define NN    50000
#define EE    800000
#define DIN   300
#define DH    96
#define DOUT  2
#define GG    64

#define BSH   6                      // bucket shift: 64 nodes per bucket
#define BKN   64                     // nodes per bucket
#define NB    ((NN + BKN - 1) / BKN) // 782 buckets

// ---------------- scratch (device globals; no allocation allowed) -----------
__device__ float g_dis[NN];
__device__ float g_h  [(size_t)NN * DH];
__device__ float g_agg[(size_t)NN * DH];
__device__ float g_pool[GG * DH];
__device__ float g_cnt [GG];
__device__ __nv_bfloat16 g_W1h[DIN * DH], g_W1l[DIN * DH];
__device__ __nv_bfloat16 g_W2h[DH * DH],  g_W2l[DH * DH];
// edge sort scratch
__device__ uint2 g_ebuf[EE];         // (src, dst) sorted by dst-bucket
__device__ int   g_bcnt[NB];
__device__ int   g_boff[NB + 1];
__device__ int   g_bcur[NB];

// ---------------- degree + bucket-count init --------------------------------
__global__ void k_deg_init() {
    int i = blockIdx.x * blockDim.x + threadIdx.x;
    if (i < NN) g_dis[i] = 1.0f;            // +1 self loop
    if (i < NB) g_bcnt[i] = 0;
}
__global__ void k_deg_count(const int* __restrict__ dst) {
    int e = blockIdx.x * blockDim.x + threadIdx.x;
    if (e < EE) atomicAdd(&g_dis[dst[e]], 1.0f);
}
__global__ void k_deg_finish() {
    int i = blockIdx.x * blockDim.x + threadIdx.x;
    if (i < NN) g_dis[i] = rsqrtf(g_dis[i]);
    if (i < GG * DH) g_pool[i] = 0.0f;
    if (i < GG)      g_cnt[i]  = 0.0f;
}

// ---------------- weight split: W -> bf16 hi + bf16 lo ----------------------
__global__ void k_wsplit(const float* __restrict__ W1, const float* __restrict__ W2) {
    int i = blockIdx.x * blockDim.x + threadIdx.x;
    if (i < DIN * DH) {
        float f = W1[i];
        __nv_bfloat16 hi = __float2bfloat16(f);
        g_W1h[i] = hi;
        g_W1l[i] = __float2bfloat16(f - __bfloat162float(hi));
    }
    if (i < DH * DH) {
        float f = W2[i];
        __nv_bfloat16 hi = __float2bfloat16(f);
        g_W2h[i] = hi;
        g_W2l[i] = __float2bfloat16(f - __bfloat162float(hi));
    }
}

// ---------------- edge counting sort by dst bucket ---------------------------
__global__ void __launch_bounds__(256)
k_hist(const int* __restrict__ dst) {
    __shared__ int h[NB];
    for (int i = threadIdx.x; i < NB; i += 256) h[i] = 0;
    __syncthreads();
    for (int e = blockIdx.x * blockDim.x + threadIdx.x; e < EE;
         e += gridDim.x * blockDim.x)
        atomicAdd(&h[dst[e] >> BSH], 1);
    __syncthreads();
    for (int i = threadIdx.x; i < NB; i += 256)
        if (h[i]) atomicAdd(&g_bcnt[i], h[i]);
}
__global__ void k_scan() {              // 1 block, 1024 threads
    __shared__ int sh[NB];
    int t = threadIdx.x;
    for (int i = t; i < NB; i += 1024) sh[i] = g_bcnt[i];
    __syncthreads();
    for (int off = 1; off < NB; off <<= 1) {
        int v = (t >= off && t < NB) ? sh[t - off] : 0;
        __syncthreads();
        if (t < NB) sh[t] += v;
        __syncthreads();
    }
    if (t < NB) {
        g_boff[t + 1] = sh[t];
        g_bcur[t] = (t == 0) ? 0 : sh[t - 1];
    }
    if (t == 0) g_boff[0] = 0;
}
__global__ void __launch_bounds__(256)
k_reorder(const int* __restrict__ src, const int* __restrict__ dst) {
    int e = blockIdx.x * blockDim.x + threadIdx.x;
    if (e >= EE) return;
    int d = dst[e];
    int pos = atomicAdd(&g_bcur[d >> BSH], 1);
    g_ebuf[pos] = make_uint2((unsigned)src[e], (unsigned)d);
}

// ---------------- mma helpers ------------------------------------------------
__device__ __forceinline__ unsigned smem_u32(const void* p) {
    return (unsigned)__cvta_generic_to_shared(p);
}
#define LDSM_X4(r, addr) \
    asm volatile("ldmatrix.sync.aligned.m8n8.x4.shared.b16 {%0,%1,%2,%3},[%4];" \
                 : "=r"((r)[0]), "=r"((r)[1]), "=r"((r)[2]), "=r"((r)[3]) : "r"(addr))
#define LDSM_X2_T(r, addr) \
    asm volatile("ldmatrix.sync.aligned.m8n8.x2.trans.shared.b16 {%0,%1},[%2];" \
                 : "=r"((r)[0]), "=r"((r)[1]) : "r"(addr))
#define MMA_BF16(d, a, b) \
    asm volatile("mma.sync.aligned.m16n8k16.row.col.f32.bf16.bf16.f32 " \
                 "{%0,%1,%2,%3},{%4,%5,%6,%7},{%8,%9},{%0,%1,%2,%3};" \
                 : "+f"((d)[0]), "+f"((d)[1]), "+f"((d)[2]), "+f"((d)[3]) \
                 : "r"((a)[0]), "r"((a)[1]), "r"((a)[2]), "r"((a)[3]), \
                   "r"((b)[0]), "r"((b)[1]))

// ---------------- pipelined bf16-split tensor GEMM: out = in @ W ------------
template <int K, bool RELU_BIAS, bool IN_IS_AGG, int WSEL>
__global__ void __launch_bounds__(256, 2)
k_gemm(const float* __restrict__ in, const float* __restrict__ bias)
{
    __shared__ __nv_bfloat16 Ah[2][128 * 24], Al[2][128 * 24];
    __shared__ __nv_bfloat16 Bh[2][16 * 104], Bl[2][16 * 104];
    __shared__ float bs[DH];

    const int tid  = threadIdx.x;
    const int lane = tid & 31;
    const int wid  = tid >> 5;
    const int wm   = wid & 3;
    const int wn   = wid >> 2;
    const int r0   = blockIdx.x * 128;
    const int gidx = lane >> 2;
    const int tidx = lane & 3;

    const float* __restrict__ src_in = IN_IS_AGG ? (const float*)g_agg : in;
    const uint4* __restrict__ Wh4 =
        (const uint4*)(WSEL == 1 ? (const void*)g_W1h : (const void*)g_W2h);
    const uint4* __restrict__ Wl4 =
        (const uint4*)(WSEL == 1 ? (const void*)g_W1l : (const void*)g_W2l);

    if (RELU_BIAS) { if (tid < DH) bs[tid] = bias[tid]; }

    float acc[2][6][4];
#pragma unroll
    for (int mt = 0; mt < 2; mt++)
#pragma unroll
        for (int nt = 0; nt < 6; nt++)
#pragma unroll
            for (int q = 0; q < 4; q++) acc[mt][nt][q] = 0.0f;

    unsigned a_h0[2], a_l0[2];
#pragma unroll
    for (int mt = 0; mt < 2; mt++) {
        int row = wm * 32 + mt * 16 + (lane & 15);
        int col = (lane >> 4) * 8;
        a_h0[mt] = smem_u32(&Ah[0][row * 24 + col]);
        a_l0[mt] = smem_u32(&Al[0][row * 24 + col]);
    }
    unsigned b_h0[6], b_l0[6];
#pragma unroll
    for (int nt = 0; nt < 6; nt++) {
        int krow  = lane & 15;
        int cbase = wn * 48 + nt * 8;
        b_h0[nt] = smem_u32(&Bh[0][krow * 104 + cbase]);
        b_l0[nt] = smem_u32(&Bl[0][krow * 104 + cbase]);
    }
    const unsigned A_STRIDE = 128 * 24 * 2;
    const unsigned B_STRIDE = 16 * 104 * 2;

    float4 pa[2];
    uint4  pb[2];

    auto load_stage = [&](int k0) {
#pragma unroll
        for (int t = 0; t < 2; t++) {
            int idx = tid + t * 256;
            int row = idx >> 2, q = idx & 3;
            int gr = r0 + row, gk = k0 + q * 4;
            pa[t] = make_float4(0.f, 0.f, 0.f, 0.f);
            if (gr < NN && gk + 4 <= K)
                pa[t] = *reinterpret_cast<const float4*>(src_in + (size_t)gr * K + gk);
        }
#pragma unroll
        for (int t = 0; t < 2; t++) {
            int idx = tid + t * 256;
            if (idx < 384) {
                int half = (idx >= 192);
                int j  = idx - half * 192;
                int kk = j / 12, c = j % 12;
                int gk = k0 + kk;
                pb[t] = make_uint4(0u, 0u, 0u, 0u);
                if (gk < K)
                    pb[t] = (half ? Wl4 : Wh4)[gk * 12 + c];
            }
        }
    };

    auto store_stage = [&](int buf, int k0) {
#pragma unroll
        for (int t = 0; t < 2; t++) {
            int idx = tid + t * 256;
            int row = idx >> 2, q = idx & 3;
            float e[4] = {pa[t].x, pa[t].y, pa[t].z, pa[t].w};
            unsigned hp[2], lp[2];
#pragma unroll
            for (int p = 0; p < 2; p++) {
                float f0 = e[p * 2], f1 = e[p * 2 + 1];
                if (RELU_BIAS) {
                    int gk = k0 + q * 4 + p * 2;
                    f0 = fmaxf(f0 + bs[gk], 0.0f);
                    f1 = fmaxf(f1 + bs[gk + 1], 0.0f);
                }
                __nv_bfloat162 h2 = make_bfloat162(__float2bfloat16(f0),
                                                   __float2bfloat16(f1));
                __nv_bfloat162 l2 = make_bfloat162(
                    __float2bfloat16(f0 - __bfloat162float(h2.x)),
                    __float2bfloat16(f1 - __bfloat162float(h2.y)));
                hp[p] = *reinterpret_cast<unsigned*>(&h2);
                lp[p] = *reinterpret_cast<unsigned*>(&l2);
            }
            *reinterpret_cast<uint2*>(&Ah[buf][row * 24 + q * 4]) = make_uint2(hp[0], hp[1]);
            *reinterpret_cast<uint2*>(&Al[buf][row * 24 + q * 4]) = make_uint2(lp[0], lp[1]);
        }
#pragma unroll
        for (int t = 0; t < 2; t++) {
            int idx = tid + t * 256;
            if (idx < 384) {
                int half = (idx >= 192);
                int j  = idx - half * 192;
                int kk = j / 12, c = j % 12;
                __nv_bfloat16* dstp = half ? Bl[buf] : Bh[buf];
                *reinterpret_cast<uint4*>(&dstp[kk * 104 + c * 8]) = pb[t];
            }
        }
    };

    const int nstage = (K + 15) / 16;
    load_stage(0);
    __syncthreads();

    for (int s = 0; s < nstage; s++) {
        const int buf = s & 1;
        store_stage(buf, s * 16);
        __syncthreads();
        if (s + 1 < nstage) load_stage((s + 1) * 16);

        const unsigned ao = buf * A_STRIDE, bo = buf * B_STRIDE;
        unsigned ah[2][4], al[2][4], bh[6][2], bl[6][2];
#pragma unroll
        for (int mt = 0; mt < 2; mt++) {
            LDSM_X4(ah[mt], a_h0[mt] + ao);
            LDSM_X4(al[mt], a_l0[mt] + ao);
        }
#pragma unroll
        for (int nt = 0; nt < 6; nt++) {
            LDSM_X2_T(bh[nt], b_h0[nt] + bo);
            LDSM_X2_T(bl[nt], b_l0[nt] + bo);
        }
#pragma unroll
        for (int mt = 0; mt < 2; mt++)
#pragma unroll
            for (int nt = 0; nt < 6; nt++) {
                MMA_BF16(acc[mt][nt], ah[mt], bh[nt]);
                MMA_BF16(acc[mt][nt], ah[mt], bl[nt]);
                MMA_BF16(acc[mt][nt], al[mt], bh[nt]);
            }
    }

#pragma unroll
    for (int mt = 0; mt < 2; mt++) {
        int rbase = r0 + wm * 32 + mt * 16 + gidx;
#pragma unroll
        for (int half = 0; half < 2; half++) {
            int r = rbase + half * 8;
            if (r >= NN) continue;
            float ds = g_dis[r];
            float d2 = ds * ds;
#pragma unroll
            for (int nt = 0; nt < 6; nt++) {
                int c = wn * 48 + nt * 8 + tidx * 2;
                float v0 = acc[mt][nt][half * 2 + 0];
                float v1 = acc[mt][nt][half * 2 + 1];
                size_t o = (size_t)r * 96 + c;
                *reinterpret_cast<float2*>(g_h + o)   = make_float2(v0, v1);
                *reinterpret_cast<float2*>(g_agg + o) = make_float2(v0 * d2, v1 * d2);
            }
        }
    }
}

// ---------------- bucketed scatter: one block per 64-node dst bucket --------
// smem accumulate (atomics), single non-atomic flush to g_agg.
__global__ void __launch_bounds__(256)
k_scatter_b()
{
    __shared__ alignas(16) float acc[BKN * 96];   // 24 KB
    const int b   = blockIdx.x;
    const int tid = threadIdx.x;
    const int wid = tid >> 5, lane = tid & 31;

    for (int i = tid; i < BKN * 96; i += 256) acc[i] = 0.0f;
    __syncthreads();

    const int beg = g_boff[b], end = g_boff[b + 1];

    for (int base = beg + wid * 8; base < end; base += 64) {
        const int cnt = min(8, end - base);
        int s = 0, d = 0; float nrm = 0.0f;
        if (lane < cnt) {
            uint2 e = g_ebuf[base + lane];
            s = (int)e.x; d = (int)e.y;
            nrm = g_dis[s] * g_dis[d];
        }
        // phase 1: issue all 6 gathers (MLP), phase 2: smem atomics
        float4 v[6];
        int    lo6[6];
        float  nn6[6];
        bool   act[6];
#pragma unroll
        for (int r = 0; r < 6; r++) {
            int i  = lane + 32 * r;       // < 192
            int eL = i / 24, ch = i % 24;
            int ss = __shfl_sync(0xffffffffu, s, eL);
            int dd = __shfl_sync(0xffffffffu, d, eL);
            nn6[r] = __shfl_sync(0xffffffffu, nrm, eL);
            act[r] = (eL < cnt);
            lo6[r] = (dd & (BKN - 1)) * 96 + ch * 4;
            v[r] = act[r]
                 ? *reinterpret_cast<const float4*>(g_h + (size_t)ss * 96 + ch * 4)
                 : make_float4(0.f, 0.f, 0.f, 0.f);
        }
#pragma unroll
        for (int r = 0; r < 6; r++) {
            if (!act[r]) continue;
            float nn = nn6[r];
            atomicAdd(&acc[lo6[r] + 0], v[r].x * nn);
            atomicAdd(&acc[lo6[r] + 1], v[r].y * nn);
            atomicAdd(&acc[lo6[r] + 2], v[r].z * nn);
            atomicAdd(&acc[lo6[r] + 3], v[r].w * nn);
        }
    }
    __syncthreads();

    // flush: block owns nodes [b*64, b*64+64) exclusively
    const int node0 = b * BKN;
    for (int i = tid; i < BKN * 24; i += 256) {        // 24 float4 per node
        int node = node0 + i / 24;
        if (node >= NN) break;
        float4 a = *reinterpret_cast<const float4*>(&acc[i * 4]);
        float4* p = reinterpret_cast<float4*>(g_agg + (size_t)node0 * 96) + i;
        float4 cur = *p;
        cur.x += a.x; cur.y += a.y; cur.z += a.z; cur.w += a.w;
        *p = cur;
    }
}

// ---------------- pooling ----------------------------------------------------
__global__ void __launch_bounds__(96)
k_pool(const float* __restrict__ b2, const int* __restrict__ batch)
{
    int c  = threadIdx.x;
    int r0 = blockIdx.x * 64;
    int re = min(r0 + 64, NN);
    if (r0 >= NN) return;
    float bb = b2[c];
    float acc = 0.0f;
    int cur = batch[r0];
    int run = 0;
    for (int r = r0; r < re; r++) {
        int g = batch[r];
        if (g != cur) {
            atomicAdd(&g_pool[cur * DH + c], acc);
            if (c == 0) atomicAdd(&g_cnt[cur], (float)run);
            acc = 0.0f; run = 0; cur = g;
        }
        acc += fmaxf(g_agg[(size_t)r * 96 + c] + bb, 0.0f);
        run++;
    }
    atomicAdd(&g_pool[cur * DH + c], acc);
    if (c == 0) atomicAdd(&g_cnt[cur], (float)run);
}

// ---------------- head -------------------------------------------------------
__global__ void k_fc(const float* __restrict__ Wfc, const float* __restrict__ bfc,
                     float* __restrict__ out)
{
    int t = threadIdx.x;
    if (t >= GG * DOUT) return;
    int g = t >> 1, o = t & 1;
    float cn = fmaxf(g_cnt[g], 1.0f);
    float s = bfc[o];
    for (int c = 0; c < DH; c++)
        s += (g_pool[g * DH + c] / cn) * Wfc[c * DOUT + o];
    out[g * DOUT + o] = s;
}

// ---------------- launch ------------------------------------------------------
extern "C" void kernel_launch(void* const* d_in, const int* in_sizes, int n_in,
                              void* d_out, int out_size)
{
    const float* x    = (const float*)d_in[0];
    const float* W1   = (const float*)d_in[1];
    const float* b1   = (const float*)d_in[2];
    const float* W2   = (const float*)d_in[3];
    const float* b2   = (const float*)d_in[4];
    const float* Wfc  = (const float*)d_in[5];
    const float* bfc  = (const float*)d_in[6];
    const int*   src  = (const int*)d_in[7];
    const int*   dst  = (const int*)d_in[8];
    const int*   batch= (const int*)d_in[9];
    float* out = (float*)d_out;

    const int nb_n = (NN + 255) / 256;
    const int nb_e = (EE + 255) / 256;
    const int nb_g = (NN + 127) / 128;
    const int nb_p = (NN + 63) / 64;

    k_wsplit    <<<(DIN * DH + 255) / 256, 256>>>(W1, W2);
    k_deg_init  <<<nb_n, 256>>>();
    k_deg_count <<<nb_e, 256>>>(dst);
    k_deg_finish<<<nb_n, 256>>>();

    // edge counting sort by dst bucket (reused by both layers)
    k_hist   <<<256, 256>>>(dst);
    k_scan   <<<1, 1024>>>();
    k_reorder<<<nb_e, 256>>>(src, dst);

    // layer 1
    k_gemm<DIN, false, false, 1><<<nb_g, 256>>>(x, b1);
    k_scatter_b<<<NB, 256>>>();

    // layer 2
    k_gemm<DH, true, true, 2><<<nb_g, 256>>>(nullptr, b1);
    k_scatter_b<<<NB, 256>>>();

    k_pool<<<nb_p, 96>>>(b2, batch);
    k_fc  <<<1, 128>>>(Wfc, bfc, out);
}

// round 7
// speedup vs baseline: 2.8945x; 2.8945x over previous
#include <cuda_runtime.h>
#include <cuda_bf16.h>
#include <math.h>

#define NN    50000
#define EE    800000
#define DIN   300
#define DH    96
#define DOUT  2
#define GG    64
#define SCB   196                    // scan blocks: ceil(50000/256)

// ---------------- scratch (device globals; no allocation allowed) -----------
__device__ float g_dis[NN];
__device__ float g_h  [(size_t)NN * DH];
__device__ float g_agg[(size_t)NN * DH];
__device__ float g_pool[GG * DH];
__device__ float g_cnt [GG];
__device__ __nv_bfloat16 g_W1h[DIN * DH], g_W1l[DIN * DH];
__device__ __nv_bfloat16 g_W2h[DH * DH],  g_W2l[DH * DH];
// CSR scratch
__device__ int   g_ncnt[NN];
__device__ int   g_tmp [NN];
__device__ int   g_bsum[256];
__device__ int   g_noff[NN + 1];
__device__ int   g_ncur[NN];
__device__ uint2 g_emeta[EE];        // (src, nrm as uint) sorted by dst

// ---------------- degree + per-node edge count -------------------------------
__global__ void k_deg_init() {
    int i = blockIdx.x * blockDim.x + threadIdx.x;
    if (i < NN) { g_dis[i] = 1.0f; g_ncnt[i] = 0; }   // +1 self loop
}
__global__ void k_deg_count(const int* __restrict__ dst) {
    int e = blockIdx.x * blockDim.x + threadIdx.x;
    if (e < EE) {
        int d = dst[e];
        atomicAdd(&g_dis[d], 1.0f);
        atomicAdd(&g_ncnt[d], 1);
    }
}
__global__ void k_deg_finish() {
    int i = blockIdx.x * blockDim.x + threadIdx.x;
    if (i < NN) g_dis[i] = rsqrtf(g_dis[i]);
    if (i < GG * DH) g_pool[i] = 0.0f;
    if (i < GG)      g_cnt[i]  = 0.0f;
}

// ---------------- weight split: W -> bf16 hi + bf16 lo ----------------------
__global__ void k_wsplit(const float* __restrict__ W1, const float* __restrict__ W2) {
    int i = blockIdx.x * blockDim.x + threadIdx.x;
    if (i < DIN * DH) {
        float f = W1[i];
        __nv_bfloat16 hi = __float2bfloat16(f);
        g_W1h[i] = hi;
        g_W1l[i] = __float2bfloat16(f - __bfloat162float(hi));
    }
    if (i < DH * DH) {
        float f = W2[i];
        __nv_bfloat16 hi = __float2bfloat16(f);
        g_W2h[i] = hi;
        g_W2l[i] = __float2bfloat16(f - __bfloat162float(hi));
    }
}

// ---------------- 3-kernel exclusive scan over g_ncnt -> g_noff -------------
__global__ void __launch_bounds__(256) k_scanA() {
    __shared__ int sh[256];
    int t  = threadIdx.x;
    int gi = blockIdx.x * 256 + t;
    int v  = (gi < NN) ? g_ncnt[gi] : 0;
    sh[t] = v; __syncthreads();
#pragma unroll
    for (int off = 1; off < 256; off <<= 1) {
        int u = (t >= off) ? sh[t - off] : 0;
        __syncthreads();
        sh[t] += u;
        __syncthreads();
    }
    if (gi < NN) g_tmp[gi] = sh[t];                   // inclusive within block
    if (t == 255) g_bsum[blockIdx.x] = sh[255];
}
__global__ void k_scanB() {           // 1 block, 256 threads
    __shared__ int sh[256];
    int t = threadIdx.x;
    sh[t] = (t < SCB) ? g_bsum[t] : 0;
    __syncthreads();
#pragma unroll
    for (int off = 1; off < 256; off <<= 1) {
        int u = (t >= off) ? sh[t - off] : 0;
        __syncthreads();
        sh[t] += u;
        __syncthreads();
    }
    g_bsum[t] = sh[t];
}
__global__ void __launch_bounds__(256) k_scanC() {
    int gi = blockIdx.x * 256 + threadIdx.x;
    if (gi >= NN) return;
    int base = (blockIdx.x > 0) ? g_bsum[blockIdx.x - 1] : 0;
    int inc  = g_tmp[gi] + base;                      // inclusive scan
    g_noff[gi + 1] = inc;
    g_ncur[gi]     = inc - g_ncnt[gi];                // start offset
    if (gi == 0) g_noff[0] = 0;
}
__global__ void __launch_bounds__(256)
k_reorder(const int* __restrict__ src, const int* __restrict__ dst) {
    int e = blockIdx.x * blockDim.x + threadIdx.x;
    if (e >= EE) return;
    int s = src[e], d = dst[e];
    int pos = atomicAdd(&g_ncur[d], 1);
    float nrm = g_dis[s] * g_dis[d];
    g_emeta[pos] = make_uint2((unsigned)s, __float_as_uint(nrm));
}

// ---------------- mma helpers ------------------------------------------------
__device__ __forceinline__ unsigned smem_u32(const void* p) {
    return (unsigned)__cvta_generic_to_shared(p);
}
#define LDSM_X4(r, addr) \
    asm volatile("ldmatrix.sync.aligned.m8n8.x4.shared.b16 {%0,%1,%2,%3},[%4];" \
                 : "=r"((r)[0]), "=r"((r)[1]), "=r"((r)[2]), "=r"((r)[3]) : "r"(addr))
#define LDSM_X2_T(r, addr) \
    asm volatile("ldmatrix.sync.aligned.m8n8.x2.trans.shared.b16 {%0,%1},[%2];" \
                 : "=r"((r)[0]), "=r"((r)[1]) : "r"(addr))
#define MMA_BF16(d, a, b) \
    asm volatile("mma.sync.aligned.m16n8k16.row.col.f32.bf16.bf16.f32 " \
                 "{%0,%1,%2,%3},{%4,%5,%6,%7},{%8,%9},{%0,%1,%2,%3};" \
                 : "+f"((d)[0]), "+f"((d)[1]), "+f"((d)[2]), "+f"((d)[3]) \
                 : "r"((a)[0]), "r"((a)[1]), "r"((a)[2]), "r"((a)[3]), \
                   "r"((b)[0]), "r"((b)[1]))

// ---------------- pipelined bf16-split tensor GEMM: out = in @ W ------------
template <int K, bool RELU_BIAS, bool IN_IS_AGG, int WSEL>
__global__ void __launch_bounds__(256, 2)
k_gemm(const float* __restrict__ in, const float* __restrict__ bias)
{
    __shared__ __nv_bfloat16 Ah[2][128 * 24], Al[2][128 * 24];
    __shared__ __nv_bfloat16 Bh[2][16 * 104], Bl[2][16 * 104];
    __shared__ float bs[DH];

    const int tid  = threadIdx.x;
    const int lane = tid & 31;
    const int wid  = tid >> 5;
    const int wm   = wid & 3;
    const int wn   = wid >> 2;
    const int r0   = blockIdx.x * 128;
    const int gidx = lane >> 2;
    const int tidx = lane & 3;

    const float* __restrict__ src_in = IN_IS_AGG ? (const float*)g_agg : in;
    const uint4* __restrict__ Wh4 =
        (const uint4*)(WSEL == 1 ? (const void*)g_W1h : (const void*)g_W2h);
    const uint4* __restrict__ Wl4 =
        (const uint4*)(WSEL == 1 ? (const void*)g_W1l : (const void*)g_W2l);

    if (RELU_BIAS) { if (tid < DH) bs[tid] = bias[tid]; }

    float acc[2][6][4];
#pragma unroll
    for (int mt = 0; mt < 2; mt++)
#pragma unroll
        for (int nt = 0; nt < 6; nt++)
#pragma unroll
            for (int q = 0; q < 4; q++) acc[mt][nt][q] = 0.0f;

    unsigned a_h0[2], a_l0[2];
#pragma unroll
    for (int mt = 0; mt < 2; mt++) {
        int row = wm * 32 + mt * 16 + (lane & 15);
        int col = (lane >> 4) * 8;
        a_h0[mt] = smem_u32(&Ah[0][row * 24 + col]);
        a_l0[mt] = smem_u32(&Al[0][row * 24 + col]);
    }
    unsigned b_h0[6], b_l0[6];
#pragma unroll
    for (int nt = 0; nt < 6; nt++) {
        int krow  = lane & 15;
        int cbase = wn * 48 + nt * 8;
        b_h0[nt] = smem_u32(&Bh[0][krow * 104 + cbase]);
        b_l0[nt] = smem_u32(&Bl[0][krow * 104 + cbase]);
    }
    const unsigned A_STRIDE = 128 * 24 * 2;
    const unsigned B_STRIDE = 16 * 104 * 2;

    float4 pa[2];
    uint4  pb[2];

    auto load_stage = [&](int k0) {
#pragma unroll
        for (int t = 0; t < 2; t++) {
            int idx = tid + t * 256;
            int row = idx >> 2, q = idx & 3;
            int gr = r0 + row, gk = k0 + q * 4;
            pa[t] = make_float4(0.f, 0.f, 0.f, 0.f);
            if (gr < NN && gk + 4 <= K)
                pa[t] = *reinterpret_cast<const float4*>(src_in + (size_t)gr * K + gk);
        }
#pragma unroll
        for (int t = 0; t < 2; t++) {
            int idx = tid + t * 256;
            if (idx < 384) {
                int half = (idx >= 192);
                int j  = idx - half * 192;
                int kk = j / 12, c = j % 12;
                int gk = k0 + kk;
                pb[t] = make_uint4(0u, 0u, 0u, 0u);
                if (gk < K)
                    pb[t] = (half ? Wl4 : Wh4)[gk * 12 + c];
            }
        }
    };

    auto store_stage = [&](int buf, int k0) {
#pragma unroll
        for (int t = 0; t < 2; t++) {
            int idx = tid + t * 256;
            int row = idx >> 2, q = idx & 3;
            float e[4] = {pa[t].x, pa[t].y, pa[t].z, pa[t].w};
            unsigned hp[2], lp[2];
#pragma unroll
            for (int p = 0; p < 2; p++) {
                float f0 = e[p * 2], f1 = e[p * 2 + 1];
                if (RELU_BIAS) {
                    int gk = k0 + q * 4 + p * 2;
                    f0 = fmaxf(f0 + bs[gk], 0.0f);
                    f1 = fmaxf(f1 + bs[gk + 1], 0.0f);
                }
                __nv_bfloat162 h2 = make_bfloat162(__float2bfloat16(f0),
                                                   __float2bfloat16(f1));
                __nv_bfloat162 l2 = make_bfloat162(
                    __float2bfloat16(f0 - __bfloat162float(h2.x)),
                    __float2bfloat16(f1 - __bfloat162float(h2.y)));
                hp[p] = *reinterpret_cast<unsigned*>(&h2);
                lp[p] = *reinterpret_cast<unsigned*>(&l2);
            }
            *reinterpret_cast<uint2*>(&Ah[buf][row * 24 + q * 4]) = make_uint2(hp[0], hp[1]);
            *reinterpret_cast<uint2*>(&Al[buf][row * 24 + q * 4]) = make_uint2(lp[0], lp[1]);
        }
#pragma unroll
        for (int t = 0; t < 2; t++) {
            int idx = tid + t * 256;
            if (idx < 384) {
                int half = (idx >= 192);
                int j  = idx - half * 192;
                int kk = j / 12, c = j % 12;
                __nv_bfloat16* dstp = half ? Bl[buf] : Bh[buf];
                *reinterpret_cast<uint4*>(&dstp[kk * 104 + c * 8]) = pb[t];
            }
        }
    };

    const int nstage = (K + 15) / 16;
    load_stage(0);
    __syncthreads();

    for (int s = 0; s < nstage; s++) {
        const int buf = s & 1;
        store_stage(buf, s * 16);
        __syncthreads();
        if (s + 1 < nstage) load_stage((s + 1) * 16);

        const unsigned ao = buf * A_STRIDE, bo = buf * B_STRIDE;
        unsigned ah[2][4], al[2][4], bh[6][2], bl[6][2];
#pragma unroll
        for (int mt = 0; mt < 2; mt++) {
            LDSM_X4(ah[mt], a_h0[mt] + ao);
            LDSM_X4(al[mt], a_l0[mt] + ao);
        }
#pragma unroll
        for (int nt = 0; nt < 6; nt++) {
            LDSM_X2_T(bh[nt], b_h0[nt] + bo);
            LDSM_X2_T(bl[nt], b_l0[nt] + bo);
        }
#pragma unroll
        for (int mt = 0; mt < 2; mt++)
#pragma unroll
            for (int nt = 0; nt < 6; nt++) {
                MMA_BF16(acc[mt][nt], ah[mt], bh[nt]);
                MMA_BF16(acc[mt][nt], ah[mt], bl[nt]);
                MMA_BF16(acc[mt][nt], al[mt], bh[nt]);
            }
    }

#pragma unroll
    for (int mt = 0; mt < 2; mt++) {
        int rbase = r0 + wm * 32 + mt * 16 + gidx;
#pragma unroll
        for (int half = 0; half < 2; half++) {
            int r = rbase + half * 8;
            if (r >= NN) continue;
            float ds = g_dis[r];
            float d2 = ds * ds;
#pragma unroll
            for (int nt = 0; nt < 6; nt++) {
                int c = wn * 48 + nt * 8 + tidx * 2;
                float v0 = acc[mt][nt][half * 2 + 0];
                float v1 = acc[mt][nt][half * 2 + 1];
                size_t o = (size_t)r * 96 + c;
                *reinterpret_cast<float2*>(g_h + o)   = make_float2(v0, v1);
                *reinterpret_cast<float2*>(g_agg + o) = make_float2(v0 * d2, v1 * d2);
            }
        }
    }
}

// ---------------- CSR scatter: one warp per dst node -------------------------
// Lane owns cols (lane, lane+32, lane+64). No atomics: warp exclusively owns
// its node's g_agg row (self-loop term already seeded by GEMM epilogue).
__global__ void __launch_bounds__(256)
k_scatter_csr()
{
    int w    = (blockIdx.x * 256 + threadIdx.x) >> 5;   // node id
    int lane = threadIdx.x & 31;
    if (w >= NN) return;
    const int beg = g_noff[w], end = g_noff[w + 1];

    float a0 = 0.f, a1 = 0.f, a2 = 0.f;
    uint2 m = (beg < end) ? g_emeta[beg] : make_uint2(0u, 0u);
    for (int e = beg; e < end; e++) {
        uint2 mn = (e + 1 < end) ? g_emeta[e + 1] : make_uint2(0u, 0u);
        float nrm = __uint_as_float(m.y);
        const float* row = g_h + (size_t)m.x * 96;
        a0 = fmaf(row[lane],      nrm, a0);
        a1 = fmaf(row[lane + 32], nrm, a1);
        a2 = fmaf(row[lane + 64], nrm, a2);
        m = mn;
    }
    float* o = g_agg + (size_t)w * 96;
    o[lane]      += a0;
    o[lane + 32] += a1;
    o[lane + 64] += a2;
}

// ---------------- pooling ----------------------------------------------------
__global__ void __launch_bounds__(96)
k_pool(const float* __restrict__ b2, const int* __restrict__ batch)
{
    int c  = threadIdx.x;
    int r0 = blockIdx.x * 64;
    int re = min(r0 + 64, NN);
    if (r0 >= NN) return;
    float bb = b2[c];
    float acc = 0.0f;
    int cur = batch[r0];
    int run = 0;
    for (int r = r0; r < re; r++) {
        int g = batch[r];
        if (g != cur) {
            atomicAdd(&g_pool[cur * DH + c], acc);
            if (c == 0) atomicAdd(&g_cnt[cur], (float)run);
            acc = 0.0f; run = 0; cur = g;
        }
        acc += fmaxf(g_agg[(size_t)r * 96 + c] + bb, 0.0f);
        run++;
    }
    atomicAdd(&g_pool[cur * DH + c], acc);
    if (c == 0) atomicAdd(&g_cnt[cur], (float)run);
}

// ---------------- head -------------------------------------------------------
__global__ void k_fc(const float* __restrict__ Wfc, const float* __restrict__ bfc,
                     float* __restrict__ out)
{
    int t = threadIdx.x;
    if (t >= GG * DOUT) return;
    int g = t >> 1, o = t & 1;
    float cn = fmaxf(g_cnt[g], 1.0f);
    float s = bfc[o];
    for (int c = 0; c < DH; c++)
        s += (g_pool[g * DH + c] / cn) * Wfc[c * DOUT + o];
    out[g * DOUT + o] = s;
}

// ---------------- launch ------------------------------------------------------
extern "C" void kernel_launch(void* const* d_in, const int* in_sizes, int n_in,
                              void* d_out, int out_size)
{
    const float* x    = (const float*)d_in[0];
    const float* W1   = (const float*)d_in[1];
    const float* b1   = (const float*)d_in[2];
    const float* W2   = (const float*)d_in[3];
    const float* b2   = (const float*)d_in[4];
    const float* Wfc  = (const float*)d_in[5];
    const float* bfc  = (const float*)d_in[6];
    const int*   src  = (const int*)d_in[7];
    const int*   dst  = (const int*)d_in[8];
    const int*   batch= (const int*)d_in[9];
    float* out = (float*)d_out;

    const int nb_n = (NN + 255) / 256;
    const int nb_e = (EE + 255) / 256;
    const int nb_g = (NN + 127) / 128;
    const int nb_p = (NN + 63) / 64;
    const int nb_s = (NN * 32 + 255) / 256;   // one warp per node

    k_wsplit    <<<(DIN * DH + 255) / 256, 256>>>(W1, W2);
    k_deg_init  <<<nb_n, 256>>>();
    k_deg_count <<<nb_e, 256>>>(dst);
    k_deg_finish<<<nb_n, 256>>>();

    // CSR build (reused by both layers)
    k_scanA  <<<SCB, 256>>>();
    k_scanB  <<<1, 256>>>();
    k_scanC  <<<SCB, 256>>>();
    k_reorder<<<nb_e, 256>>>(src, dst);

    // layer 1
    k_gemm<DIN, false, false, 1><<<nb_g, 256>>>(x, b1);
    k_scatter_csr<<<nb_s, 256>>>();

    // layer 2
    k_gemm<DH, true, true, 2><<<nb_g, 256>>>(nullptr, b1);
    k_scatter_csr<<<nb_s, 256>>>();

    k_pool<<<nb_p, 96>>>(b2, batch);
    k_fc  <<<1, 128>>>(Wfc, bfc, out);
}

// round 8
// speedup vs baseline: 3.1512x; 1.0887x over previous
#include <cuda_runtime.h>
#include <cuda_bf16.h>
#include <math.h>

#define NN    50000
#define EE    800000
#define DIN   300
#define DH    96
#define DOUT  2
#define GG    64
#define SCB   196                    // scan blocks: ceil(50000/256)

// ---------------- scratch (device globals; no allocation allowed) -----------
__device__ float g_dis[NN];
__device__ float g_h  [(size_t)NN * DH];    // h * dis (pre-scaled!)
__device__ float g_agg[(size_t)NN * DH];
__device__ float g_pool[GG * DH];
__device__ float g_cnt [GG];
__device__ __nv_bfloat16 g_W1h[DIN * DH], g_W1l[DIN * DH];
__device__ __nv_bfloat16 g_W2h[DH * DH],  g_W2l[DH * DH];
// CSR scratch
__device__ int      g_ncnt[NN];
__device__ int      g_tmp [NN];
__device__ int      g_bsum[256];
__device__ int      g_noff[NN + 1];
__device__ int      g_ncur[NN];
__device__ unsigned g_esrc[EE];      // src ids sorted by dst

// ---------------- weight split + init ---------------------------------------
__global__ void k_wsplit(const float* __restrict__ W1, const float* __restrict__ W2) {
    int i = blockIdx.x * blockDim.x + threadIdx.x;
    if (i < DIN * DH) {
        float f = W1[i];
        __nv_bfloat16 hi = __float2bfloat16(f);
        g_W1h[i] = hi;
        g_W1l[i] = __float2bfloat16(f - __bfloat162float(hi));
    }
    if (i < DH * DH) {
        float f = W2[i];
        __nv_bfloat16 hi = __float2bfloat16(f);
        g_W2h[i] = hi;
        g_W2l[i] = __float2bfloat16(f - __bfloat162float(hi));
    }
    if (i < NN) g_ncnt[i] = 0;
    if (i < GG * DH) g_pool[i] = 0.0f;
    if (i < GG)      g_cnt[i]  = 0.0f;
}
__global__ void k_deg_count(const int* __restrict__ dst) {
    int e = blockIdx.x * blockDim.x + threadIdx.x;
    if (e < EE) atomicAdd(&g_ncnt[dst[e]], 1);
}
__global__ void k_deg_finish() {     // dis = rsqrt(deg+1) from int counts
    int i = blockIdx.x * blockDim.x + threadIdx.x;
    if (i < NN) g_dis[i] = rsqrtf(1.0f + (float)g_ncnt[i]);
}

// ---------------- scan (2 kernels; block-sum scan inlined in C) --------------
__global__ void __launch_bounds__(256) k_scanA() {
    __shared__ int sh[256];
    int t  = threadIdx.x;
    int gi = blockIdx.x * 256 + t;
    int v  = (gi < NN) ? g_ncnt[gi] : 0;
    sh[t] = v; __syncthreads();
#pragma unroll
    for (int off = 1; off < 256; off <<= 1) {
        int u = (t >= off) ? sh[t - off] : 0;
        __syncthreads();
        sh[t] += u;
        __syncthreads();
    }
    if (gi < NN) g_tmp[gi] = sh[t];                   // inclusive within block
    if (t == 255) g_bsum[blockIdx.x] = sh[255];
}
__global__ void __launch_bounds__(256) k_scanC() {
    __shared__ int sb[256];
    int t = threadIdx.x;
    sb[t] = (t < SCB) ? g_bsum[t] : 0;
    __syncthreads();
#pragma unroll
    for (int off = 1; off < 256; off <<= 1) {
        int u = (t >= off) ? sb[t - off] : 0;
        __syncthreads();
        sb[t] += u;
        __syncthreads();
    }
    int gi = blockIdx.x * 256 + t;
    if (gi >= NN) return;
    int base = (blockIdx.x > 0) ? sb[blockIdx.x - 1] : 0;
    int inc  = g_tmp[gi] + base;
    g_noff[gi + 1] = inc;
    g_ncur[gi]     = inc - g_ncnt[gi];
    if (gi == 0) g_noff[0] = 0;
}
__global__ void __launch_bounds__(256)
k_reorder(const int* __restrict__ src, const int* __restrict__ dst) {
    int e = blockIdx.x * blockDim.x + threadIdx.x;
    if (e >= EE) return;
    int pos = atomicAdd(&g_ncur[dst[e]], 1);
    g_esrc[pos] = (unsigned)src[e];
}

// ---------------- mma helpers ------------------------------------------------
__device__ __forceinline__ unsigned smem_u32(const void* p) {
    return (unsigned)__cvta_generic_to_shared(p);
}
#define LDSM_X4(r, addr) \
    asm volatile("ldmatrix.sync.aligned.m8n8.x4.shared.b16 {%0,%1,%2,%3},[%4];" \
                 : "=r"((r)[0]), "=r"((r)[1]), "=r"((r)[2]), "=r"((r)[3]) : "r"(addr))
#define LDSM_X2_T(r, addr) \
    asm volatile("ldmatrix.sync.aligned.m8n8.x2.trans.shared.b16 {%0,%1},[%2];" \
                 : "=r"((r)[0]), "=r"((r)[1]) : "r"(addr))
#define MMA_BF16(d, a, b) \
    asm volatile("mma.sync.aligned.m16n8k16.row.col.f32.bf16.bf16.f32 " \
                 "{%0,%1,%2,%3},{%4,%5,%6,%7},{%8,%9},{%0,%1,%2,%3};" \
                 : "+f"((d)[0]), "+f"((d)[1]), "+f"((d)[2]), "+f"((d)[3]) \
                 : "r"((a)[0]), "r"((a)[1]), "r"((a)[2]), "r"((a)[3]), \
                   "r"((b)[0]), "r"((b)[1]))

// ---------------- pipelined bf16-split tensor GEMM: out = in @ W ------------
// Epilogue: g_h = acc * dis (pre-scaled for scatter); g_agg = acc * dis^2.
template <int K, bool RELU_BIAS, bool IN_IS_AGG, int WSEL>
__global__ void __launch_bounds__(256, 2)
k_gemm(const float* __restrict__ in, const float* __restrict__ bias)
{
    __shared__ __nv_bfloat16 Ah[2][128 * 24], Al[2][128 * 24];
    __shared__ __nv_bfloat16 Bh[2][16 * 104], Bl[2][16 * 104];
    __shared__ float bs[DH];

    const int tid  = threadIdx.x;
    const int lane = tid & 31;
    const int wid  = tid >> 5;
    const int wm   = wid & 3;
    const int wn   = wid >> 2;
    const int r0   = blockIdx.x * 128;
    const int gidx = lane >> 2;
    const int tidx = lane & 3;

    const float* __restrict__ src_in = IN_IS_AGG ? (const float*)g_agg : in;
    const uint4* __restrict__ Wh4 =
        (const uint4*)(WSEL == 1 ? (const void*)g_W1h : (const void*)g_W2h);
    const uint4* __restrict__ Wl4 =
        (const uint4*)(WSEL == 1 ? (const void*)g_W1l : (const void*)g_W2l);

    if (RELU_BIAS) { if (tid < DH) bs[tid] = bias[tid]; }

    float acc[2][6][4];
#pragma unroll
    for (int mt = 0; mt < 2; mt++)
#pragma unroll
        for (int nt = 0; nt < 6; nt++)
#pragma unroll
            for (int q = 0; q < 4; q++) acc[mt][nt][q] = 0.0f;

    unsigned a_h0[2], a_l0[2];
#pragma unroll
    for (int mt = 0; mt < 2; mt++) {
        int row = wm * 32 + mt * 16 + (lane & 15);
        int col = (lane >> 4) * 8;
        a_h0[mt] = smem_u32(&Ah[0][row * 24 + col]);
        a_l0[mt] = smem_u32(&Al[0][row * 24 + col]);
    }
    unsigned b_h0[6], b_l0[6];
#pragma unroll
    for (int nt = 0; nt < 6; nt++) {
        int krow  = lane & 15;
        int cbase = wn * 48 + nt * 8;
        b_h0[nt] = smem_u32(&Bh[0][krow * 104 + cbase]);
        b_l0[nt] = smem_u32(&Bl[0][krow * 104 + cbase]);
    }
    const unsigned A_STRIDE = 128 * 24 * 2;
    const unsigned B_STRIDE = 16 * 104 * 2;

    float4 pa[2];
    uint4  pb[2];

    auto load_stage = [&](int k0) {
#pragma unroll
        for (int t = 0; t < 2; t++) {
            int idx = tid + t * 256;
            int row = idx >> 2, q = idx & 3;
            int gr = r0 + row, gk = k0 + q * 4;
            pa[t] = make_float4(0.f, 0.f, 0.f, 0.f);
            if (gr < NN && gk + 4 <= K)
                pa[t] = *reinterpret_cast<const float4*>(src_in + (size_t)gr * K + gk);
        }
#pragma unroll
        for (int t = 0; t < 2; t++) {
            int idx = tid + t * 256;
            if (idx < 384) {
                int half = (idx >= 192);
                int j  = idx - half * 192;
                int kk = j / 12, c = j % 12;
                int gk = k0 + kk;
                pb[t] = make_uint4(0u, 0u, 0u, 0u);
                if (gk < K)
                    pb[t] = (half ? Wl4 : Wh4)[gk * 12 + c];
            }
        }
    };

    auto store_stage = [&](int buf, int k0) {
#pragma unroll
        for (int t = 0; t < 2; t++) {
            int idx = tid + t * 256;
            int row = idx >> 2, q = idx & 3;
            float e[4] = {pa[t].x, pa[t].y, pa[t].z, pa[t].w};
            unsigned hp[2], lp[2];
#pragma unroll
            for (int p = 0; p < 2; p++) {
                float f0 = e[p * 2], f1 = e[p * 2 + 1];
                if (RELU_BIAS) {
                    int gk = k0 + q * 4 + p * 2;
                    f0 = fmaxf(f0 + bs[gk], 0.0f);
                    f1 = fmaxf(f1 + bs[gk + 1], 0.0f);
                }
                __nv_bfloat162 h2 = make_bfloat162(__float2bfloat16(f0),
                                                   __float2bfloat16(f1));
                __nv_bfloat162 l2 = make_bfloat162(
                    __float2bfloat16(f0 - __bfloat162float(h2.x)),
                    __float2bfloat16(f1 - __bfloat162float(h2.y)));
                hp[p] = *reinterpret_cast<unsigned*>(&h2);
                lp[p] = *reinterpret_cast<unsigned*>(&l2);
            }
            *reinterpret_cast<uint2*>(&Ah[buf][row * 24 + q * 4]) = make_uint2(hp[0], hp[1]);
            *reinterpret_cast<uint2*>(&Al[buf][row * 24 + q * 4]) = make_uint2(lp[0], lp[1]);
        }
#pragma unroll
        for (int t = 0; t < 2; t++) {
            int idx = tid + t * 256;
            if (idx < 384) {
                int half = (idx >= 192);
                int j  = idx - half * 192;
                int kk = j / 12, c = j % 12;
                __nv_bfloat16* dstp = half ? Bl[buf] : Bh[buf];
                *reinterpret_cast<uint4*>(&dstp[kk * 104 + c * 8]) = pb[t];
            }
        }
    };

    const int nstage = (K + 15) / 16;
    load_stage(0);
    __syncthreads();

    for (int s = 0; s < nstage; s++) {
        const int buf = s & 1;
        store_stage(buf, s * 16);
        __syncthreads();
        if (s + 1 < nstage) load_stage((s + 1) * 16);

        const unsigned ao = buf * A_STRIDE, bo = buf * B_STRIDE;
        unsigned ah[2][4], al[2][4], bh[6][2], bl[6][2];
#pragma unroll
        for (int mt = 0; mt < 2; mt++) {
            LDSM_X4(ah[mt], a_h0[mt] + ao);
            LDSM_X4(al[mt], a_l0[mt] + ao);
        }
#pragma unroll
        for (int nt = 0; nt < 6; nt++) {
            LDSM_X2_T(bh[nt], b_h0[nt] + bo);
            LDSM_X2_T(bl[nt], b_l0[nt] + bo);
        }
#pragma unroll
        for (int mt = 0; mt < 2; mt++)
#pragma unroll
            for (int nt = 0; nt < 6; nt++) {
                MMA_BF16(acc[mt][nt], ah[mt], bh[nt]);
                MMA_BF16(acc[mt][nt], ah[mt], bl[nt]);
                MMA_BF16(acc[mt][nt], al[mt], bh[nt]);
            }
    }

#pragma unroll
    for (int mt = 0; mt < 2; mt++) {
        int rbase = r0 + wm * 32 + mt * 16 + gidx;
#pragma unroll
        for (int half = 0; half < 2; half++) {
            int r = rbase + half * 8;
            if (r >= NN) continue;
            float ds = g_dis[r];
            float d2 = ds * ds;
#pragma unroll
            for (int nt = 0; nt < 6; nt++) {
                int c = wn * 48 + nt * 8 + tidx * 2;
                float v0 = acc[mt][nt][half * 2 + 0];
                float v1 = acc[mt][nt][half * 2 + 1];
                size_t o = (size_t)r * 96 + c;
                *reinterpret_cast<float2*>(g_h + o)   = make_float2(v0 * ds, v1 * ds);
                *reinterpret_cast<float2*>(g_agg + o) = make_float2(v0 * d2, v1 * d2);
            }
        }
    }
}

// ---------------- CSR scatter: one warp per dst node -------------------------
// g_h rows are pre-scaled by dis[src]; accumulate plain sums, scale by dis[w].
// 4x unrolled for MLP (12 row loads in flight).
__global__ void __launch_bounds__(256)
k_scatter_csr()
{
    int w    = (blockIdx.x * 256 + threadIdx.x) >> 5;   // node id
    int lane = threadIdx.x & 31;
    if (w >= NN) return;
    const int beg = g_noff[w], end = g_noff[w + 1];

    float a0 = 0.f, a1 = 0.f, a2 = 0.f;
    int e = beg;
    for (; e + 4 <= end; e += 4) {
        unsigned s0 = g_esrc[e],     s1 = g_esrc[e + 1];
        unsigned s2 = g_esrc[e + 2], s3 = g_esrc[e + 3];
        const float* r0 = g_h + (size_t)s0 * 96;
        const float* r1 = g_h + (size_t)s1 * 96;
        const float* r2 = g_h + (size_t)s2 * 96;
        const float* r3 = g_h + (size_t)s3 * 96;
        float v00 = r0[lane], v01 = r0[lane + 32], v02 = r0[lane + 64];
        float v10 = r1[lane], v11 = r1[lane + 32], v12 = r1[lane + 64];
        float v20 = r2[lane], v21 = r2[lane + 32], v22 = r2[lane + 64];
        float v30 = r3[lane], v31 = r3[lane + 32], v32 = r3[lane + 64];
        a0 += (v00 + v10) + (v20 + v30);
        a1 += (v01 + v11) + (v21 + v31);
        a2 += (v02 + v12) + (v22 + v32);
    }
    for (; e < end; e++) {
        const float* r = g_h + (size_t)g_esrc[e] * 96;
        a0 += r[lane]; a1 += r[lane + 32]; a2 += r[lane + 64];
    }
    float dw = g_dis[w];
    float* o = g_agg + (size_t)w * 96;
    o[lane]      += a0 * dw;
    o[lane + 32] += a1 * dw;
    o[lane + 64] += a2 * dw;
}

// ---------------- pooling ----------------------------------------------------
__global__ void __launch_bounds__(96)
k_pool(const float* __restrict__ b2, const int* __restrict__ batch)
{
    int c  = threadIdx.x;
    int r0 = blockIdx.x * 64;
    int re = min(r0 + 64, NN);
    if (r0 >= NN) return;
    float bb = b2[c];
    float acc = 0.0f;
    int cur = batch[r0];
    int run = 0;
    for (int r = r0; r < re; r++) {
        int g = batch[r];
        if (g != cur) {
            atomicAdd(&g_pool[cur * DH + c], acc);
            if (c == 0) atomicAdd(&g_cnt[cur], (float)run);
            acc = 0.0f; run = 0; cur = g;
        }
        acc += fmaxf(g_agg[(size_t)r * 96 + c] + bb, 0.0f);
        run++;
    }
    atomicAdd(&g_pool[cur * DH + c], acc);
    if (c == 0) atomicAdd(&g_cnt[cur], (float)run);
}

// ---------------- head -------------------------------------------------------
__global__ void k_fc(const float* __restrict__ Wfc, const float* __restrict__ bfc,
                     float* __restrict__ out)
{
    int t = threadIdx.x;
    if (t >= GG * DOUT) return;
    int g = t >> 1, o = t & 1;
    float cn = fmaxf(g_cnt[g], 1.0f);
    float s = bfc[o];
    for (int c = 0; c < DH; c++)
        s += (g_pool[g * DH + c] / cn) * Wfc[c * DOUT + o];
    out[g * DOUT + o] = s;
}

// ---------------- launch ------------------------------------------------------
extern "C" void kernel_launch(void* const* d_in, const int* in_sizes, int n_in,
                              void* d_out, int out_size)
{
    const float* x    = (const float*)d_in[0];
    const float* W1   = (const float*)d_in[1];
    const float* b1   = (const float*)d_in[2];
    const float* W2   = (const float*)d_in[3];
    const float* b2   = (const float*)d_in[4];
    const float* Wfc  = (const float*)d_in[5];
    const float* bfc  = (const float*)d_in[6];
    const int*   src  = (const int*)d_in[7];
    const int*   dst  = (const int*)d_in[8];
    const int*   batch= (const int*)d_in[9];
    float* out = (float*)d_out;

    const int nb_n = (NN + 255) / 256;
    const int nb_e = (EE + 255) / 256;
    const int nb_g = (NN + 127) / 128;
    const int nb_p = (NN + 63) / 64;
    const int nb_s = (NN * 32 + 255) / 256;   // one warp per node

    k_wsplit    <<<nb_n, 256>>>(W1, W2);      // + ncnt/pool/cnt init
    k_deg_count <<<nb_e, 256>>>(dst);
    k_scanA     <<<SCB, 256>>>();
    k_scanC     <<<SCB, 256>>>();
    k_reorder   <<<nb_e, 256>>>(src, dst);
    k_deg_finish<<<nb_n, 256>>>();

    // layer 1
    k_gemm<DIN, false, false, 1><<<nb_g, 256>>>(x, b1);
    k_scatter_csr<<<nb_s, 256>>>();

    // layer 2
    k_gemm<DH, true, true, 2><<<nb_g, 256>>>(nullptr, b1);
    k_scatter_csr<<<nb_s, 256>>>();

    k_pool<<<nb_p, 96>>>(b2, batch);
    k_fc  <<<1, 128>>>(Wfc, bfc, out);
}